// round 10
// baseline (speedup 1.0000x reference)
#include <cuda_runtime.h>
#include <cuda_fp16.h>
#include <cstdint>

#define B_ 2
#define S_ 4096
#define E_ 1024
#define H_ 16
#define D_ 64
#define NTOK (B_*S_)
#define NELEM (NTOK*E_)
#define KAUG 1088   // 1024 + 64 (bias row + zero pad) = 17 tiles of BK=64
#define LOG2E 1.4426950408889634f

__device__ __half g_q[NELEM];
__device__ __half g_k[NELEM];
__device__ __half g_v[NELEM];
__device__ __half g_xh[NTOK * KAUG];       // fp16 X, augmented
__device__ __half g_wh[3 * E_ * KAUG];     // fp16 W (scaled), bias folded

__device__ __forceinline__ void cp16(unsigned int dst, const void* src) {
    asm volatile("cp.async.cg.shared.global [%0], [%1], 16;" :: "r"(dst), "l"(src));
}
__device__ __forceinline__ unsigned int sptr(const void* p) {
    return (unsigned int)__cvta_generic_to_shared(p);
}
__device__ __forceinline__ unsigned hexp2pk(float a, float b) {
    __half2 hv = __floats2half2_rn(a, b);
    unsigned r;
    asm("ex2.approx.f16x2 %0, %1;" : "=r"(r) : "r"(*(unsigned*)&hv));
    return r;
}
__device__ __forceinline__ void mma16816(float* d, const unsigned* a, const unsigned* b) {
    asm volatile("mma.sync.aligned.m16n8k16.row.col.f32.f16.f16.f32 "
                 "{%0,%1,%2,%3}, {%4,%5,%6,%7}, {%8,%9}, {%0,%1,%2,%3};"
                 : "+f"(d[0]), "+f"(d[1]), "+f"(d[2]), "+f"(d[3])
                 : "r"(a[0]), "r"(a[1]), "r"(a[2]), "r"(a[3]), "r"(b[0]), "r"(b[1]));
}
__device__ __forceinline__ void ldsm4(unsigned* r, unsigned addr) {
    asm volatile("ldmatrix.sync.aligned.m8n8.x4.shared.b16 {%0,%1,%2,%3}, [%4];"
                 : "=r"(r[0]), "=r"(r[1]), "=r"(r[2]), "=r"(r[3]) : "r"(addr));
}
__device__ __forceinline__ void ldsm4t(unsigned* r, unsigned addr) {
    asm volatile("ldmatrix.sync.aligned.m8n8.x4.trans.shared.b16 {%0,%1,%2,%3}, [%4];"
                 : "=r"(r[0]), "=r"(r[1]), "=r"(r[2]), "=r"(r[3]) : "r"(addr));
}

// ---------------------------------------------------------------------------
// One-time conversions fp32 -> fp16 with K-augmentation (8 elems / thread).
// ---------------------------------------------------------------------------
__global__ void __launch_bounds__(256) cvt_x(const float* __restrict__ X) {
    int idx8 = blockIdx.x * 256 + threadIdx.x;
    if (idx8 >= NTOK * (KAUG / 8)) return;
    int row = idx8 / (KAUG / 8);
    int c = (idx8 - row * (KAUG / 8)) * 8;
    __half2 h[4];
    if (c < 1024) {
        const float4* src = (const float4*)(X + (size_t)row * 1024 + c);
        float4 v0 = src[0], v1 = src[1];
        h[0] = __floats2half2_rn(v0.x, v0.y);
        h[1] = __floats2half2_rn(v0.z, v0.w);
        h[2] = __floats2half2_rn(v1.x, v1.y);
        h[3] = __floats2half2_rn(v1.z, v1.w);
    } else {
        h[0] = __floats2half2_rn(c == 1024 ? 1.0f : 0.0f, 0.0f);   // bias row
        h[1] = h[2] = h[3] = __floats2half2_rn(0.0f, 0.0f);
    }
    *(uint4*)(g_xh + (size_t)row * KAUG + c) = *(uint4*)h;
}

__global__ void __launch_bounds__(256) cvt_w(const float* __restrict__ qw, const float* __restrict__ qb,
                                             const float* __restrict__ kw, const float* __restrict__ kb,
                                             const float* __restrict__ vw, const float* __restrict__ vb) {
    const int which = blockIdx.y;
    const float* w = (which == 0) ? qw : ((which == 1) ? kw : vw);
    const float* b = (which == 0) ? qb : ((which == 1) ? kb : vb);
    const float scale = (which == 0) ? 0.125f * LOG2E : 1.0f;   // log2e folded into Q

    int idx8 = blockIdx.x * 256 + threadIdx.x;
    if (idx8 >= E_ * (KAUG / 8)) return;
    int n = idx8 / (KAUG / 8);
    int c = (idx8 - n * (KAUG / 8)) * 8;
    __half2 h[4];
    if (c < 1024) {
        const float4* src = (const float4*)(w + (size_t)n * 1024 + c);
        float4 v0 = src[0], v1 = src[1];
        h[0] = __floats2half2_rn(v0.x * scale, v0.y * scale);
        h[1] = __floats2half2_rn(v0.z * scale, v0.w * scale);
        h[2] = __floats2half2_rn(v1.x * scale, v1.y * scale);
        h[3] = __floats2half2_rn(v1.z * scale, v1.w * scale);
    } else {
        h[0] = __floats2half2_rn(c == 1024 ? b[n] * scale : 0.0f, 0.0f);
        h[1] = h[2] = h[3] = __floats2half2_rn(0.0f, 0.0f);
    }
    *(uint4*)(g_wh + (size_t)which * E_ * KAUG + (size_t)n * KAUG + c) = *(uint4*)h;
}

// ---------------------------------------------------------------------------
// Projection GEMM v2: raw mma.16816 + ldmatrix. BM=128, BN=256, BK=64.
// 8 warps, each 64x64. 3-stage cp.async ring, ONE syncthreads per K-tile.
// C = Xh @ Wh^T, bias folded via augmented K row.
// ---------------------------------------------------------------------------
#define GAP 72      // smem stride in halves (64 + 8): conflict-free ldmatrix
#define GA_BYTES (128 * GAP * 2)
#define GB_BYTES (256 * GAP * 2)
#define GEMM_SMEM (3 * (GA_BYTES + GB_BYTES))

__global__ void __launch_bounds__(256, 1) gemm_qkv() {
    extern __shared__ char smg[];

    const int which = blockIdx.z;
    const __half* wbase = g_wh + (size_t)which * E_ * KAUG;
    __half* C = (which == 0) ? g_q : ((which == 1) ? g_k : g_v);

    const int m0 = blockIdx.y * 128;
    const int n0 = blockIdx.x * 256;
    const int tid = threadIdx.x;
    const int warp = tid >> 5;
    const int lane = tid & 31;
    const int wm = warp >> 2;    // 0..1 -> 64 rows
    const int wn = warp & 3;     // 0..3 -> 64 cols

    float acc[4][8][4];
#pragma unroll
    for (int mi = 0; mi < 4; mi++)
#pragma unroll
        for (int nj = 0; nj < 8; nj++)
#pragma unroll
            for (int e = 0; e < 4; e++) acc[mi][nj][e] = 0.f;

    auto issue = [&](int kt, int s) {
        __half* Ad = (__half*)(smg + s * GA_BYTES);
        __half* Bd = (__half*)(smg + 3 * GA_BYTES + s * GB_BYTES);
#pragma unroll
        for (int i = 0; i < 4; i++) {          // A: 128 rows x 8 chunks
            int c = tid + i * 256;
            int row = c >> 3, kc = (c & 7) * 8;
            cp16(sptr(&Ad[row * GAP + kc]), g_xh + (size_t)(m0 + row) * KAUG + kt * 64 + kc);
        }
#pragma unroll
        for (int i = 0; i < 8; i++) {          // B: 256 rows x 8 chunks
            int c = tid + i * 256;
            int row = c >> 3, kc = (c & 7) * 8;
            cp16(sptr(&Bd[row * GAP + kc]), wbase + (size_t)(n0 + row) * KAUG + kt * 64 + kc);
        }
        asm volatile("cp.async.commit_group;" ::);
    };

    issue(0, 0);
    issue(1, 1);

    const int arow = wm * 64 + (lane & 7) + ((lane & 8) ? 8 : 0);
    const int acolb = (lane & 16) ? 8 : 0;
    const int brow0 = wn * 64 + ((lane & 16) ? 8 : 0) + (lane & 7);
    const int bcolb = (lane & 8) ? 8 : 0;

    for (int kt = 0; kt < 17; kt++) {
        if (kt + 1 < 17) { asm volatile("cp.async.wait_group 1;" ::); }
        else             { asm volatile("cp.async.wait_group 0;" ::); }
        __syncthreads();
        if (kt + 2 < 17) issue(kt + 2, (kt + 2) % 3);

        const int s = kt % 3;
        const __half* As = (const __half*)(smg + s * GA_BYTES);
        const __half* Bsm = (const __half*)(smg + 3 * GA_BYTES + s * GB_BYTES);

#pragma unroll
        for (int t = 0; t < 4; t++) {          // 4 k-steps of 16
            unsigned af[4][4];
#pragma unroll
            for (int mi = 0; mi < 4; mi++)
                ldsm4(af[mi], sptr(&As[(arow + mi * 16 - wm * 64 + wm * 64) * GAP + t * 16 + acolb]));
            unsigned bf[4][4];
#pragma unroll
            for (int p = 0; p < 4; p++)
                ldsm4(bf[p], sptr(&Bsm[(brow0 + p * 16) * GAP + t * 16 + bcolb]));
#pragma unroll
            for (int mi = 0; mi < 4; mi++) {
#pragma unroll
                for (int p = 0; p < 4; p++) {
                    mma16816(acc[mi][2 * p],     af[mi], bf[p]);
                    mma16816(acc[mi][2 * p + 1], af[mi], bf[p] + 2);
                }
            }
        }
    }

    // Epilogue: direct half2 stores from accumulator fragments.
    const int r0 = lane >> 2;
    const int c0 = (lane & 3) * 2;
#pragma unroll
    for (int mi = 0; mi < 4; mi++) {
        const int row0 = m0 + wm * 64 + mi * 16 + r0;
#pragma unroll
        for (int nj = 0; nj < 8; nj++) {
            const int col = n0 + wn * 64 + nj * 8 + c0;
            __half2 h0 = __floats2half2_rn(acc[mi][nj][0], acc[mi][nj][1]);
            __half2 h1 = __floats2half2_rn(acc[mi][nj][2], acc[mi][nj][3]);
            *(__half2*)(C + (size_t)row0 * 1024 + col) = h0;
            *(__half2*)(C + (size_t)(row0 + 8) * 1024 + col) = h1;
        }
    }
}

// ---------------------------------------------------------------------------
// Banded attention (unchanged from round 9): raw mma + ldmatrix, register
// softmax in log2 domain with ex2.approx.f16x2, cp.async double-buffered K/V.
// ---------------------------------------------------------------------------
#define AP 72
#define QS_OFF 0
#define KS_OFF (128*AP*2)
#define VS_OFF (KS_OFF + 2*64*AP*2)
#define FML_OFF (VS_OFF + 2*64*AP*2)
#define ATTN_SMEM (FML_OFF + 2*64*4)

__global__ void __launch_bounds__(256, 2) attn_mma(const int* __restrict__ am,
                                                   float* __restrict__ out) {
    extern __shared__ char smb[];
    __half* Qs = (__half*)(smb + QS_OFF);
    float* fml = (float*)(smb + FML_OFF);

    const int chunk0 = blockIdx.x * 128;
    const int h = blockIdx.y;
    const int b = blockIdx.z;
    const int tid = threadIdx.x;
    const int lane = tid & 31;
    const int warp = tid >> 5;
    const int q0 = warp * 16;
    const size_t base = (size_t)b * S_ * E_ + h * 64;

#pragma unroll
    for (int r = 0; r < 4; r++) {
        int c = tid + r * 256;
        int row = c >> 3, off = (c & 7) * 8;
        *(uint4*)(&Qs[row * AP + off]) =
            *(const uint4*)(g_q + base + (size_t)(chunk0 + row) * E_ + off);
    }

    const int kt_start = (chunk0 >= 256) ? 0 : ((256 - chunk0) / 64);
    const int kt_end = min(10, (S_ + 192 - chunk0) / 64 + 1);

    auto issueKV = [&](int kt, int s) {
        const int kglob = chunk0 - 256 + kt * 64;
        __half* Kd = (__half*)(smb + KS_OFF + s * (64 * AP * 2));
        __half* Vd = (__half*)(smb + VS_OFF + s * (64 * AP * 2));
#pragma unroll
        for (int i = 0; i < 2; i++) {
            int c = tid + i * 256;
            int row = c >> 3, off = (c & 7) * 8;
            size_t g = base + (size_t)(kglob + row) * E_ + off;
            cp16(sptr(&Kd[row * AP + off]), g_k + g);
            cp16(sptr(&Vd[row * AP + off]), g_v + g);
        }
        asm volatile("cp.async.commit_group;" ::);
        if (tid < 64)
            fml[s * 64 + tid] =
                (am[(size_t)b * S_ + kglob + tid] != 0) ? (-10000.f * LOG2E) : 0.f;
    };

    issueKV(kt_start, 0);
    __syncthreads();

    unsigned qa[4][4];
    {
        int qrow = q0 + (lane & 7) + ((lane & 8) ? 8 : 0);
        int qc = (lane & 16) ? 8 : 0;
#pragma unroll
        for (int t = 0; t < 4; t++)
            ldsm4(qa[t], sptr(&Qs[qrow * AP + t * 16 + qc]));
    }

    float oacc[8][4];
#pragma unroll
    for (int j = 0; j < 8; j++)
#pragma unroll
        for (int e = 0; e < 4; e++) oacc[j][e] = 0.f;
    float lsum0 = 0.f, lsum1 = 0.f;
    const int col0 = (lane & 3) * 2;
    const int rq0 = chunk0 + q0 + (lane >> 2);

    for (int kt = kt_start; kt < kt_end; kt++) {
        const int s = (kt - kt_start) & 1;
        const int kglob = chunk0 - 256 + kt * 64;
        if (kt + 1 < kt_end) {
            issueKV(kt + 1, s ^ 1);
            asm volatile("cp.async.wait_group 1;" ::);
        } else {
            asm volatile("cp.async.wait_group 0;" ::);
        }
        __syncthreads();
        const __half* Ks = (const __half*)(smb + KS_OFF + s * (64 * AP * 2));
        const __half* Vs = (const __half*)(smb + VS_OFF + s * (64 * AP * 2));
        const float* fm = fml + s * 64;

#pragma unroll
        for (int sub = 0; sub < 2; sub++) {
            const int klocal = sub * 32;
            const int lo = kglob + klocal - (chunk0 + q0 + 15);
            const int hi = kglob + klocal + 31 - (chunk0 + q0);
            if (lo > 256 || hi < -256) continue;

            float sacc[4][4];
#pragma unroll
            for (int j = 0; j < 4; j++)
#pragma unroll
                for (int e = 0; e < 4; e++) sacc[j][e] = 0.f;
#pragma unroll
            for (int t = 0; t < 4; t++) {
#pragma unroll
                for (int p = 0; p < 2; p++) {
                    unsigned kb[4];
                    int krow = klocal + p * 16 + ((lane & 16) ? 8 : 0) + (lane & 7);
                    int kcol = t * 16 + ((lane & 8) ? 8 : 0);
                    ldsm4(kb, sptr(&Ks[krow * AP + kcol]));
                    mma16816(sacc[2 * p], qa[t], kb);
                    mma16816(sacc[2 * p + 1], qa[t], kb + 2);
                }
            }

            unsigned pa[2][4];
#pragma unroll
            for (int jj = 0; jj < 4; jj++) {
                const int keyg = kglob + klocal + jj * 8 + col0;
                const float f0 = fm[klocal + jj * 8 + col0];
                const float f1 = fm[klocal + jj * 8 + col0 + 1];
                const int r00 = keyg - rq0;
                const float t00 = (r00 >= -256 && r00 <= 256) ? sacc[jj][0] + f0 : -1e5f;
                const float t01 = (r00 + 1 >= -256 && r00 + 1 <= 256) ? sacc[jj][1] + f1 : -1e5f;
                const float t10 = (r00 - 8 >= -256 && r00 - 8 <= 256) ? sacc[jj][2] + f0 : -1e5f;
                const float t11 = (r00 - 7 >= -256 && r00 - 7 <= 256) ? sacc[jj][3] + f1 : -1e5f;
                unsigned p0 = hexp2pk(t00, t01);
                unsigned p1 = hexp2pk(t10, t11);
                float2 f0v = __half22float2(*(__half2*)&p0);
                float2 f1v = __half22float2(*(__half2*)&p1);
                lsum0 += f0v.x + f0v.y;
                lsum1 += f1v.x + f1v.y;
                pa[jj >> 1][(jj & 1) * 2 + 0] = p0;
                pa[jj >> 1][(jj & 1) * 2 + 1] = p1;
            }

#pragma unroll
            for (int tt = 0; tt < 2; tt++) {
                const int k0 = klocal + tt * 16;
#pragma unroll
                for (int dp = 0; dp < 4; dp++) {
                    unsigned vb[4];
                    int vrow = k0 + ((lane & 8) ? 8 : 0) + (lane & 7);
                    int vcol = dp * 16 + ((lane & 16) ? 8 : 0);
                    ldsm4t(vb, sptr(&Vs[vrow * AP + vcol]));
                    mma16816(oacc[2 * dp], pa[tt], vb);
                    mma16816(oacc[2 * dp + 1], pa[tt], vb + 2);
                }
            }
        }
        __syncthreads();
    }

    lsum0 += __shfl_xor_sync(0xffffffffu, lsum0, 1);
    lsum0 += __shfl_xor_sync(0xffffffffu, lsum0, 2);
    lsum1 += __shfl_xor_sync(0xffffffffu, lsum1, 1);
    lsum1 += __shfl_xor_sync(0xffffffffu, lsum1, 2);
    const float inv0 = 1.0f / lsum0;
    const float inv1 = 1.0f / lsum1;

    float* o0 = out + base + (size_t)rq0 * E_;
    float* o1 = out + base + (size_t)(rq0 + 8) * E_;
#pragma unroll
    for (int j = 0; j < 8; j++) {
        float2 v0 = make_float2(oacc[j][0] * inv0, oacc[j][1] * inv0);
        float2 v1 = make_float2(oacc[j][2] * inv1, oacc[j][3] * inv1);
        *(float2*)(o0 + j * 8 + col0) = v0;
        *(float2*)(o1 + j * 8 + col0) = v1;
    }
}

// ---------------------------------------------------------------------------
extern "C" void kernel_launch(void* const* d_in, const int* in_sizes, int n_in,
                              void* d_out, int out_size) {
    const float* hs = (const float*)d_in[0];
    const int*   am = (const int*)d_in[1];
    const float* qw = (const float*)d_in[2];
    const float* qb = (const float*)d_in[3];
    const float* kw = (const float*)d_in[4];
    const float* kb = (const float*)d_in[5];
    const float* vw = (const float*)d_in[6];
    const float* vb = (const float*)d_in[7];
    float* out = (float*)d_out;

    cvt_x<<<(NTOK * (KAUG / 8) + 255) / 256, 256>>>(hs);
    dim3 gw((E_ * (KAUG / 8) + 255) / 256, 3);
    cvt_w<<<gw, 256>>>(qw, qb, kw, kb, vw, vb);

    cudaFuncSetAttribute(gemm_qkv, cudaFuncAttributeMaxDynamicSharedMemorySize, GEMM_SMEM);
    dim3 gg(E_ / 256, NTOK / 128, 3);
    gemm_qkv<<<gg, 256, GEMM_SMEM>>>();

    cudaFuncSetAttribute(attn_mma, cudaFuncAttributeMaxDynamicSharedMemorySize, ATTN_SMEM);
    dim3 ga(S_ / 128, H_, B_);
    attn_mma<<<ga, 256, ATTN_SMEM>>>(am, out);
}

// round 11
// speedup vs baseline: 1.1382x; 1.1382x over previous
#include <cuda_runtime.h>
#include <cuda_fp16.h>
#include <cstdint>

#define B_ 2
#define S_ 4096
#define E_ 1024
#define H_ 16
#define D_ 64
#define NTOK (B_*S_)
#define NELEM (NTOK*E_)
#define KAUG 1088   // 1024 + 64 (bias row + zero pad) = 17 tiles of BK=64
#define LOG2E 1.4426950408889634f

__device__ __half g_q[NELEM];
__device__ __half g_k[NELEM];
__device__ __half g_v[NELEM];
__device__ __half g_xh[NTOK * KAUG];       // fp16 X, augmented
__device__ __half g_wh[3 * E_ * KAUG];     // fp16 W (scaled), bias folded

__device__ __forceinline__ void cp16(unsigned int dst, const void* src) {
    asm volatile("cp.async.cg.shared.global [%0], [%1], 16;" :: "r"(dst), "l"(src));
}
__device__ __forceinline__ unsigned int sptr(const void* p) {
    return (unsigned int)__cvta_generic_to_shared(p);
}
__device__ __forceinline__ unsigned hexp2pk(float a, float b) {
    __half2 hv = __floats2half2_rn(a, b);
    unsigned r;
    asm("ex2.approx.f16x2 %0, %1;" : "=r"(r) : "r"(*(unsigned*)&hv));
    return r;
}
__device__ __forceinline__ void mma16816(float* d, const unsigned* a, const unsigned* b) {
    asm volatile("mma.sync.aligned.m16n8k16.row.col.f32.f16.f16.f32 "
                 "{%0,%1,%2,%3}, {%4,%5,%6,%7}, {%8,%9}, {%0,%1,%2,%3};"
                 : "+f"(d[0]), "+f"(d[1]), "+f"(d[2]), "+f"(d[3])
                 : "r"(a[0]), "r"(a[1]), "r"(a[2]), "r"(a[3]), "r"(b[0]), "r"(b[1]));
}
__device__ __forceinline__ void ldsm4(unsigned* r, unsigned addr) {
    asm volatile("ldmatrix.sync.aligned.m8n8.x4.shared.b16 {%0,%1,%2,%3}, [%4];"
                 : "=r"(r[0]), "=r"(r[1]), "=r"(r[2]), "=r"(r[3]) : "r"(addr));
}
__device__ __forceinline__ void ldsm4t(unsigned* r, unsigned addr) {
    asm volatile("ldmatrix.sync.aligned.m8n8.x4.trans.shared.b16 {%0,%1,%2,%3}, [%4];"
                 : "=r"(r[0]), "=r"(r[1]), "=r"(r[2]), "=r"(r[3]) : "r"(addr));
}

// ---------------------------------------------------------------------------
// One-time conversions fp32 -> fp16 with K-augmentation (8 elems / thread).
// ---------------------------------------------------------------------------
__global__ void __launch_bounds__(256) cvt_x(const float* __restrict__ X) {
    int idx8 = blockIdx.x * 256 + threadIdx.x;
    if (idx8 >= NTOK * (KAUG / 8)) return;
    int row = idx8 / (KAUG / 8);
    int c = (idx8 - row * (KAUG / 8)) * 8;
    __half2 h[4];
    if (c < 1024) {
        const float4* src = (const float4*)(X + (size_t)row * 1024 + c);
        float4 v0 = src[0], v1 = src[1];
        h[0] = __floats2half2_rn(v0.x, v0.y);
        h[1] = __floats2half2_rn(v0.z, v0.w);
        h[2] = __floats2half2_rn(v1.x, v1.y);
        h[3] = __floats2half2_rn(v1.z, v1.w);
    } else {
        h[0] = __floats2half2_rn(c == 1024 ? 1.0f : 0.0f, 0.0f);   // bias row
        h[1] = h[2] = h[3] = __floats2half2_rn(0.0f, 0.0f);
    }
    *(uint4*)(g_xh + (size_t)row * KAUG + c) = *(uint4*)h;
}

__global__ void __launch_bounds__(256) cvt_w(const float* __restrict__ qw, const float* __restrict__ qb,
                                             const float* __restrict__ kw, const float* __restrict__ kb,
                                             const float* __restrict__ vw, const float* __restrict__ vb) {
    const int which = blockIdx.y;
    const float* w = (which == 0) ? qw : ((which == 1) ? kw : vw);
    const float* b = (which == 0) ? qb : ((which == 1) ? kb : vb);
    const float scale = (which == 0) ? 0.125f * LOG2E : 1.0f;   // log2e folded into Q

    int idx8 = blockIdx.x * 256 + threadIdx.x;
    if (idx8 >= E_ * (KAUG / 8)) return;
    int n = idx8 / (KAUG / 8);
    int c = (idx8 - n * (KAUG / 8)) * 8;
    __half2 h[4];
    if (c < 1024) {
        const float4* src = (const float4*)(w + (size_t)n * 1024 + c);
        float4 v0 = src[0], v1 = src[1];
        h[0] = __floats2half2_rn(v0.x * scale, v0.y * scale);
        h[1] = __floats2half2_rn(v0.z * scale, v0.w * scale);
        h[2] = __floats2half2_rn(v1.x * scale, v1.y * scale);
        h[3] = __floats2half2_rn(v1.z * scale, v1.w * scale);
    } else {
        h[0] = __floats2half2_rn(c == 1024 ? b[n] * scale : 0.0f, 0.0f);
        h[1] = h[2] = h[3] = __floats2half2_rn(0.0f, 0.0f);
    }
    *(uint4*)(g_wh + (size_t)which * E_ * KAUG + (size_t)n * KAUG + c) = *(uint4*)h;
}

// ---------------------------------------------------------------------------
// Projection GEMM v3: raw mma.16816 + ldmatrix. BM=128, BN=128, BK=64.
// 8 warps (2x4), each 64x32 (acc = 64 regs). 2-stage cp.async, 2 blocks/SM.
// C = Xh @ Wh^T, bias folded via augmented K row.
// ---------------------------------------------------------------------------
#define GAP2 72                          // halves: 64 + 8 pad
#define GSTG (128 * GAP2 * 2)            // bytes per matrix per stage (18432)
#define GEMM_SMEM (4 * GSTG)             // A[2] + B[2] = 73728 B

__global__ void __launch_bounds__(256, 2) gemm_qkv() {
    extern __shared__ char smg[];

    const int which = blockIdx.z;
    const __half* wbase = g_wh + (size_t)which * E_ * KAUG;
    __half* C = (which == 0) ? g_q : ((which == 1) ? g_k : g_v);

    const int m0 = blockIdx.y * 128;
    const int n0 = blockIdx.x * 128;
    const int tid = threadIdx.x;
    const int warp = tid >> 5;
    const int lane = tid & 31;
    const int wm = warp >> 2;    // 0..1 -> 64 rows
    const int wn = warp & 3;     // 0..3 -> 32 cols

    float acc[4][4][4];
#pragma unroll
    for (int mi = 0; mi < 4; mi++)
#pragma unroll
        for (int nj = 0; nj < 4; nj++)
#pragma unroll
            for (int e = 0; e < 4; e++) acc[mi][nj][e] = 0.f;

    auto issue = [&](int kt, int s) {
        __half* Ad = (__half*)(smg + s * GSTG);
        __half* Bd = (__half*)(smg + 2 * GSTG + s * GSTG);
#pragma unroll
        for (int i = 0; i < 4; i++) {          // 128 rows x 8 chunks of 8 halves
            int c = tid + i * 256;
            int row = c >> 3, kc = (c & 7) * 8;
            cp16(sptr(&Ad[row * GAP2 + kc]), g_xh + (size_t)(m0 + row) * KAUG + kt * 64 + kc);
            cp16(sptr(&Bd[row * GAP2 + kc]), wbase + (size_t)(n0 + row) * KAUG + kt * 64 + kc);
        }
        asm volatile("cp.async.commit_group;" ::);
    };

    const int arbase = wm * 64 + (lane & 7) + ((lane & 8) ? 8 : 0);
    const int acolb = (lane & 16) ? 8 : 0;
    const int brbase = wn * 32 + ((lane & 16) ? 8 : 0) + (lane & 7);
    const int bcolb = (lane & 8) ? 8 : 0;

    issue(0, 0);
    for (int kt = 0; kt < 17; kt++) {
        const int s = kt & 1;
        if (kt + 1 < 17) {
            issue(kt + 1, s ^ 1);
            asm volatile("cp.async.wait_group 1;" ::);
        } else {
            asm volatile("cp.async.wait_group 0;" ::);
        }
        __syncthreads();

        const __half* As = (const __half*)(smg + s * GSTG);
        const __half* Bsm = (const __half*)(smg + 2 * GSTG + s * GSTG);

#pragma unroll
        for (int t = 0; t < 4; t++) {          // 4 k-steps of 16
            unsigned af[4][4];
#pragma unroll
            for (int mi = 0; mi < 4; mi++)
                ldsm4(af[mi], sptr(&As[(arbase + mi * 16) * GAP2 + t * 16 + acolb]));
            unsigned bf[2][4];
#pragma unroll
            for (int p = 0; p < 2; p++)
                ldsm4(bf[p], sptr(&Bsm[(brbase + p * 16) * GAP2 + t * 16 + bcolb]));
#pragma unroll
            for (int mi = 0; mi < 4; mi++) {
#pragma unroll
                for (int p = 0; p < 2; p++) {
                    mma16816(acc[mi][2 * p],     af[mi], bf[p]);
                    mma16816(acc[mi][2 * p + 1], af[mi], bf[p] + 2);
                }
            }
        }
        __syncthreads();   // all warps done with stage s before it is re-filled
    }

    // Epilogue: direct half2 stores from accumulator fragments.
    const int r0 = lane >> 2;
    const int c0 = (lane & 3) * 2;
#pragma unroll
    for (int mi = 0; mi < 4; mi++) {
        const int row0 = m0 + wm * 64 + mi * 16 + r0;
#pragma unroll
        for (int nj = 0; nj < 4; nj++) {
            const int col = n0 + wn * 32 + nj * 8 + c0;
            __half2 h0 = __floats2half2_rn(acc[mi][nj][0], acc[mi][nj][1]);
            __half2 h1 = __floats2half2_rn(acc[mi][nj][2], acc[mi][nj][3]);
            *(__half2*)(C + (size_t)row0 * 1024 + col) = h0;
            *(__half2*)(C + (size_t)(row0 + 8) * 1024 + col) = h1;
        }
    }
}

// ---------------------------------------------------------------------------
// Banded attention (unchanged, known-good 74.8us): raw mma + ldmatrix,
// register softmax in log2 domain, ex2.approx.f16x2, double-buffered K/V.
// ---------------------------------------------------------------------------
#define AP 72
#define QS_OFF 0
#define KS_OFF (128*AP*2)
#define VS_OFF (KS_OFF + 2*64*AP*2)
#define FML_OFF (VS_OFF + 2*64*AP*2)
#define ATTN_SMEM (FML_OFF + 2*64*4)

__global__ void __launch_bounds__(256, 2) attn_mma(const int* __restrict__ am,
                                                   float* __restrict__ out) {
    extern __shared__ char smb[];
    __half* Qs = (__half*)(smb + QS_OFF);
    float* fml = (float*)(smb + FML_OFF);

    const int chunk0 = blockIdx.x * 128;
    const int h = blockIdx.y;
    const int b = blockIdx.z;
    const int tid = threadIdx.x;
    const int lane = tid & 31;
    const int warp = tid >> 5;
    const int q0 = warp * 16;
    const size_t base = (size_t)b * S_ * E_ + h * 64;

#pragma unroll
    for (int r = 0; r < 4; r++) {
        int c = tid + r * 256;
        int row = c >> 3, off = (c & 7) * 8;
        *(uint4*)(&Qs[row * AP + off]) =
            *(const uint4*)(g_q + base + (size_t)(chunk0 + row) * E_ + off);
    }

    const int kt_start = (chunk0 >= 256) ? 0 : ((256 - chunk0) / 64);
    const int kt_end = min(10, (S_ + 192 - chunk0) / 64 + 1);

    auto issueKV = [&](int kt, int s) {
        const int kglob = chunk0 - 256 + kt * 64;
        __half* Kd = (__half*)(smb + KS_OFF + s * (64 * AP * 2));
        __half* Vd = (__half*)(smb + VS_OFF + s * (64 * AP * 2));
#pragma unroll
        for (int i = 0; i < 2; i++) {
            int c = tid + i * 256;
            int row = c >> 3, off = (c & 7) * 8;
            size_t g = base + (size_t)(kglob + row) * E_ + off;
            cp16(sptr(&Kd[row * AP + off]), g_k + g);
            cp16(sptr(&Vd[row * AP + off]), g_v + g);
        }
        asm volatile("cp.async.commit_group;" ::);
        if (tid < 64)
            fml[s * 64 + tid] =
                (am[(size_t)b * S_ + kglob + tid] != 0) ? (-10000.f * LOG2E) : 0.f;
    };

    issueKV(kt_start, 0);
    __syncthreads();

    unsigned qa[4][4];
    {
        int qrow = q0 + (lane & 7) + ((lane & 8) ? 8 : 0);
        int qc = (lane & 16) ? 8 : 0;
#pragma unroll
        for (int t = 0; t < 4; t++)
            ldsm4(qa[t], sptr(&Qs[qrow * AP + t * 16 + qc]));
    }

    float oacc[8][4];
#pragma unroll
    for (int j = 0; j < 8; j++)
#pragma unroll
        for (int e = 0; e < 4; e++) oacc[j][e] = 0.f;
    float lsum0 = 0.f, lsum1 = 0.f;
    const int col0 = (lane & 3) * 2;
    const int rq0 = chunk0 + q0 + (lane >> 2);

    for (int kt = kt_start; kt < kt_end; kt++) {
        const int s = (kt - kt_start) & 1;
        const int kglob = chunk0 - 256 + kt * 64;
        if (kt + 1 < kt_end) {
            issueKV(kt + 1, s ^ 1);
            asm volatile("cp.async.wait_group 1;" ::);
        } else {
            asm volatile("cp.async.wait_group 0;" ::);
        }
        __syncthreads();
        const __half* Ks = (const __half*)(smb + KS_OFF + s * (64 * AP * 2));
        const __half* Vs = (const __half*)(smb + VS_OFF + s * (64 * AP * 2));
        const float* fm = fml + s * 64;

#pragma unroll
        for (int sub = 0; sub < 2; sub++) {
            const int klocal = sub * 32;
            const int lo = kglob + klocal - (chunk0 + q0 + 15);
            const int hi = kglob + klocal + 31 - (chunk0 + q0);
            if (lo > 256 || hi < -256) continue;

            float sacc[4][4];
#pragma unroll
            for (int j = 0; j < 4; j++)
#pragma unroll
                for (int e = 0; e < 4; e++) sacc[j][e] = 0.f;
#pragma unroll
            for (int t = 0; t < 4; t++) {
#pragma unroll
                for (int p = 0; p < 2; p++) {
                    unsigned kb[4];
                    int krow = klocal + p * 16 + ((lane & 16) ? 8 : 0) + (lane & 7);
                    int kcol = t * 16 + ((lane & 8) ? 8 : 0);
                    ldsm4(kb, sptr(&Ks[krow * AP + kcol]));
                    mma16816(sacc[2 * p], qa[t], kb);
                    mma16816(sacc[2 * p + 1], qa[t], kb + 2);
                }
            }

            unsigned pa[2][4];
#pragma unroll
            for (int jj = 0; jj < 4; jj++) {
                const int keyg = kglob + klocal + jj * 8 + col0;
                const float f0 = fm[klocal + jj * 8 + col0];
                const float f1 = fm[klocal + jj * 8 + col0 + 1];
                const int r00 = keyg - rq0;
                const float t00 = (r00 >= -256 && r00 <= 256) ? sacc[jj][0] + f0 : -1e5f;
                const float t01 = (r00 + 1 >= -256 && r00 + 1 <= 256) ? sacc[jj][1] + f1 : -1e5f;
                const float t10 = (r00 - 8 >= -256 && r00 - 8 <= 256) ? sacc[jj][2] + f0 : -1e5f;
                const float t11 = (r00 - 7 >= -256 && r00 - 7 <= 256) ? sacc[jj][3] + f1 : -1e5f;
                unsigned p0 = hexp2pk(t00, t01);
                unsigned p1 = hexp2pk(t10, t11);
                float2 f0v = __half22float2(*(__half2*)&p0);
                float2 f1v = __half22float2(*(__half2*)&p1);
                lsum0 += f0v.x + f0v.y;
                lsum1 += f1v.x + f1v.y;
                pa[jj >> 1][(jj & 1) * 2 + 0] = p0;
                pa[jj >> 1][(jj & 1) * 2 + 1] = p1;
            }

#pragma unroll
            for (int tt = 0; tt < 2; tt++) {
                const int k0 = klocal + tt * 16;
#pragma unroll
                for (int dp = 0; dp < 4; dp++) {
                    unsigned vb[4];
                    int vrow = k0 + ((lane & 8) ? 8 : 0) + (lane & 7);
                    int vcol = dp * 16 + ((lane & 16) ? 8 : 0);
                    ldsm4t(vb, sptr(&Vs[vrow * AP + vcol]));
                    mma16816(oacc[2 * dp], pa[tt], vb);
                    mma16816(oacc[2 * dp + 1], pa[tt], vb + 2);
                }
            }
        }
        __syncthreads();
    }

    lsum0 += __shfl_xor_sync(0xffffffffu, lsum0, 1);
    lsum0 += __shfl_xor_sync(0xffffffffu, lsum0, 2);
    lsum1 += __shfl_xor_sync(0xffffffffu, lsum1, 1);
    lsum1 += __shfl_xor_sync(0xffffffffu, lsum1, 2);
    const float inv0 = 1.0f / lsum0;
    const float inv1 = 1.0f / lsum1;

    float* o0 = out + base + (size_t)rq0 * E_;
    float* o1 = out + base + (size_t)(rq0 + 8) * E_;
#pragma unroll
    for (int j = 0; j < 8; j++) {
        float2 v0 = make_float2(oacc[j][0] * inv0, oacc[j][1] * inv0);
        float2 v1 = make_float2(oacc[j][2] * inv1, oacc[j][3] * inv1);
        *(float2*)(o0 + j * 8 + col0) = v0;
        *(float2*)(o1 + j * 8 + col0) = v1;
    }
}

// ---------------------------------------------------------------------------
extern "C" void kernel_launch(void* const* d_in, const int* in_sizes, int n_in,
                              void* d_out, int out_size) {
    const float* hs = (const float*)d_in[0];
    const int*   am = (const int*)d_in[1];
    const float* qw = (const float*)d_in[2];
    const float* qb = (const float*)d_in[3];
    const float* kw = (const float*)d_in[4];
    const float* kb = (const float*)d_in[5];
    const float* vw = (const float*)d_in[6];
    const float* vb = (const float*)d_in[7];
    float* out = (float*)d_out;

    cvt_x<<<(NTOK * (KAUG / 8) + 255) / 256, 256>>>(hs);
    dim3 gw((E_ * (KAUG / 8) + 255) / 256, 3);
    cvt_w<<<gw, 256>>>(qw, qb, kw, kb, vw, vb);

    cudaFuncSetAttribute(gemm_qkv, cudaFuncAttributeMaxDynamicSharedMemorySize, GEMM_SMEM);
    dim3 gg(E_ / 128, NTOK / 128, 3);
    gemm_qkv<<<gg, 256, GEMM_SMEM>>>();

    cudaFuncSetAttribute(attn_mma, cudaFuncAttributeMaxDynamicSharedMemorySize, ATTN_SMEM);
    dim3 ga(S_ / 128, H_, B_);
    attn_mma<<<ga, 256, ATTN_SMEM>>>(am, out);
}